// round 5
// baseline (speedup 1.0000x reference)
#include <cuda_runtime.h>
#include <math.h>

#define BB 4
#define LL 5
#define NN 20      // B*L
#define CIN 64
#define HH 256
#define WW 128

// ---------------- scratch (device globals; no allocation) ----------------
__device__ float g_neigh[NN * CIN * HH * WW];     // (20,64,256,128)  ~168MB
__device__ float g_m1[NN * 32 * 128 * 64];        // conv1 out
__device__ float g_m2[NN * 64 * 64 * 32];         // conv2 out
__device__ float g_m3[NN * 64 * 32 * 16];         // conv3 out
__device__ float g_attn[NN];                      // (4,5) softmax weights

// ---------------- K1: affine grid sample (bilinear, zero pad) ----------------
__global__ void k_gridsample(const float* __restrict__ x, const float* __restrict__ nam) {
    int n  = blockIdx.y;       // 0..19
    int yy = blockIdx.x;       // 0..255
    int xx = threadIdx.x;      // 0..127
    int b = n / LL, nl = n % LL;
    const float* t = nam + ((size_t)(b * LL * LL) + nl) * 6;   // nam[b][0][nl]
    float t00 = t[0], t01 = t[1], t02 = t[2];
    float t10 = t[3], t11 = t[4], t12 = t[5];

    float gx = (xx + 0.5f) * (2.0f / WW) - 1.0f;
    float gy = (yy + 0.5f) * (2.0f / HH) - 1.0f;
    float grx = t00 * gx + t01 * gy + t02;
    float gry = t10 * gx + t11 * gy + t12;
    float sx = ((grx + 1.0f) * WW - 1.0f) * 0.5f;
    float sy = ((gry + 1.0f) * HH - 1.0f) * 0.5f;
    float x0f = floorf(sx), y0f = floorf(sy);
    int ix0 = (int)x0f, iy0 = (int)y0f;
    int ix1 = ix0 + 1, iy1 = iy0 + 1;
    float wx1 = sx - x0f, wx0 = 1.0f - wx1;
    float wy1 = sy - y0f, wy0 = 1.0f - wy1;
    bool vx0 = (ix0 >= 0) && (ix0 < WW), vx1 = (ix1 >= 0) && (ix1 < WW);
    bool vy0 = (iy0 >= 0) && (iy0 < HH), vy1 = (iy1 >= 0) && (iy1 < HH);
    float w00 = wx0 * wy0 * ((vx0 && vy0) ? 1.f : 0.f);
    float w10 = wx1 * wy0 * ((vx1 && vy0) ? 1.f : 0.f);
    float w01 = wx0 * wy1 * ((vx0 && vy1) ? 1.f : 0.f);
    float w11 = wx1 * wy1 * ((vx1 && vy1) ? 1.f : 0.f);
    int cx0 = min(max(ix0, 0), WW - 1), cx1 = min(max(ix1, 0), WW - 1);
    int cy0 = min(max(iy0, 0), HH - 1), cy1 = min(max(iy1, 0), HH - 1);

    size_t base = (size_t)n * CIN * HH * WW;
    int o00 = cy0 * WW + cx0, o10 = cy0 * WW + cx1;
    int o01 = cy1 * WW + cx0, o11 = cy1 * WW + cx1;
    size_t ob = base + (size_t)yy * WW + xx;
    #pragma unroll 4
    for (int c = 0; c < CIN; c++) {
        const float* p = x + base + (size_t)c * (HH * WW);
        float v = w00 * p[o00] + w10 * p[o10] + w01 * p[o01] + w11 * p[o11];
        g_neigh[ob + (size_t)c * (HH * WW)] = v;
    }
}

// ---------------- K2: conv1  64->32, k4 s2 p1, 256x128 -> 128x64 ----------------
// block = (n, oy); 64 threads, one per ox; each thread accumulates all 32 ocs.
__global__ void k_conv1(const float* __restrict__ w, const float* __restrict__ bias) {
    int n = blockIdx.y, oy = blockIdx.x, ox = threadIdx.x;   // ox 0..63
    __shared__ float s_in[4][132];
    __shared__ float s_w[512];        // [oc*16 + ky*4 + kx] for current ic
    float acc[32];
    #pragma unroll
    for (int i = 0; i < 32; i++) acc[i] = 0.f;

    for (int ic = 0; ic < 64; ic++) {
        __syncthreads();
        // weights for this ic: w[oc][ic][ky][kx]
        for (int i = ox; i < 512; i += 64) {
            int oc = i >> 4, k = i & 15;
            s_w[i] = w[((oc * 64 + ic) << 4) + k];
        }
        // 4 input rows, ix in [-1,128]
        for (int j = ox; j < 4 * 130; j += 64) {
            int ky = j / 130, p = j - ky * 130;
            int ix = p - 1, iy = 2 * oy - 1 + ky;
            float v = 0.f;
            if (ix >= 0 && ix < 128 && iy >= 0 && iy < 256)
                v = g_neigh[(((size_t)n * 64 + ic) * 256 + iy) * 128 + ix];
            s_in[ky][p] = v;
        }
        __syncthreads();
        #pragma unroll
        for (int ky = 0; ky < 4; ky++)
            #pragma unroll
            for (int kx = 0; kx < 4; kx++) {
                float iv = s_in[ky][2 * ox + kx];
                #pragma unroll
                for (int oc = 0; oc < 32; oc++)
                    acc[oc] += iv * s_w[oc * 16 + ky * 4 + kx];
            }
    }
    #pragma unroll
    for (int oc = 0; oc < 32; oc++)
        g_m1[(((size_t)n * 32 + oc) * 128 + oy) * 64 + ox] = fmaxf(acc[oc] + bias[oc], 0.f);
}

// ---------------- K3: conv2  32->64, 128x64 -> 64x32 ----------------
// block = (n, oy-pair); 64 threads = 2 rows x 32 ox; each thread all 64 ocs.
__global__ void k_conv2(const float* __restrict__ w, const float* __restrict__ bias) {
    int n = blockIdx.y, p = blockIdx.x;            // p 0..31
    int tid = threadIdx.x;
    int oyl = tid >> 5, ox = tid & 31;
    int oy = p * 2 + oyl;
    __shared__ float s_in[6][68];
    __shared__ float s_w[1024];
    float acc[64];
    #pragma unroll
    for (int i = 0; i < 64; i++) acc[i] = 0.f;

    for (int ic = 0; ic < 32; ic++) {
        __syncthreads();
        for (int i = tid; i < 1024; i += 64) {
            int oc = i >> 4, k = i & 15;
            s_w[i] = w[((oc * 32 + ic) << 4) + k];
        }
        for (int j = tid; j < 6 * 66; j += 64) {
            int r = j / 66, pos = j - r * 66;
            int ix = pos - 1, iy = 4 * p - 1 + r;
            float v = 0.f;
            if (ix >= 0 && ix < 64 && iy >= 0 && iy < 128)
                v = g_m1[(((size_t)n * 32 + ic) * 128 + iy) * 64 + ix];
            s_in[r][pos] = v;
        }
        __syncthreads();
        #pragma unroll
        for (int ky = 0; ky < 4; ky++)
            #pragma unroll
            for (int kx = 0; kx < 4; kx++) {
                float iv = s_in[2 * oyl + ky][2 * ox + kx];
                #pragma unroll
                for (int oc = 0; oc < 64; oc++)
                    acc[oc] += iv * s_w[oc * 16 + ky * 4 + kx];
            }
    }
    #pragma unroll
    for (int oc = 0; oc < 64; oc++)
        g_m2[(((size_t)n * 64 + oc) * 64 + oy) * 32 + ox] = fmaxf(acc[oc] + bias[oc], 0.f);
}

// ---------------- K4: conv3  64->64, 64x32 -> 32x16 ----------------
// block = (n, oy-quad); 128 threads = 2 oc-halves x 4 rows x 16 ox; 32 ocs/thread.
__global__ void k_conv3(const float* __restrict__ w, const float* __restrict__ bias) {
    int n = blockIdx.y, q = blockIdx.x;            // q 0..7
    int tid = threadIdx.x;
    int och = tid >> 6;
    int rem = tid & 63;
    int oyl = rem >> 4, ox = rem & 15;
    int oy = q * 4 + oyl;
    __shared__ float s_in[10][36];
    __shared__ float s_w[1024];
    float acc[32];
    #pragma unroll
    for (int i = 0; i < 32; i++) acc[i] = 0.f;

    for (int ic = 0; ic < 64; ic++) {
        __syncthreads();
        for (int i = tid; i < 1024; i += 128) {
            int oc = i >> 4, k = i & 15;
            s_w[i] = w[((oc * 64 + ic) << 4) + k];
        }
        for (int j = tid; j < 10 * 34; j += 128) {
            int r = j / 34, pos = j - r * 34;
            int ix = pos - 1, iy = 8 * q - 1 + r;
            float v = 0.f;
            if (ix >= 0 && ix < 32 && iy >= 0 && iy < 64)
                v = g_m2[(((size_t)n * 64 + ic) * 64 + iy) * 32 + ix];
            s_in[r][pos] = v;
        }
        __syncthreads();
        #pragma unroll
        for (int ky = 0; ky < 4; ky++)
            #pragma unroll
            for (int kx = 0; kx < 4; kx++) {
                float iv = s_in[2 * oyl + ky][2 * ox + kx];
                #pragma unroll
                for (int i = 0; i < 32; i++)
                    acc[i] += iv * s_w[(och * 32 + i) * 16 + ky * 4 + kx];
            }
    }
    #pragma unroll
    for (int i = 0; i < 32; i++) {
        int oc = och * 32 + i;
        g_m3[(((size_t)n * 64 + oc) * 32 + oy) * 16 + ox] = fmaxf(acc[i] + bias[oc], 0.f);
    }
}

// ---------------- K5: pool + key/qry MLPs + attention softmax ----------------
__global__ void k_attn(const float* __restrict__ k1w, const float* __restrict__ k1b,
                       const float* __restrict__ k2w, const float* __restrict__ k2b,
                       const float* __restrict__ k3w, const float* __restrict__ k3b,
                       const float* __restrict__ q1w, const float* __restrict__ q1b,
                       const float* __restrict__ q2w, const float* __restrict__ q2b,
                       const float* __restrict__ q3w, const float* __restrict__ q3b,
                       const float* __restrict__ aw,  const float* __restrict__ ab) {
    int b = blockIdx.x;               // 0..3
    int tid = threadIdx.x;            // 256 threads
    int warp = tid >> 5, lane = tid & 31;
    __shared__ float s_pool[5][64];
    __shared__ float s_key[5][256];
    __shared__ float s_h1[256];
    __shared__ float s_h2[128];
    __shared__ float s_qry[32];
    __shared__ float s_q[256];
    __shared__ float s_log[5];

    // global mean pool over 32x16 per (j, c); warp-per-task
    for (int t = warp; t < 5 * 64; t += 8) {
        int j = t >> 6, c = t & 63;
        const float* p = g_m3 + ((size_t)((b * 5 + j) * 64 + c)) * 512;
        float s = 0.f;
        for (int k = lane; k < 512; k += 32) s += p[k];
        #pragma unroll
        for (int o = 16; o; o >>= 1) s += __shfl_xor_sync(0xFFFFFFFFu, s, o);
        if (lane == 0) s_pool[j][c] = s * (1.0f / 512.0f);
    }
    __syncthreads();

    // keys for 5 images
    for (int j = 0; j < 5; j++) {
        {   float a = k1b[tid];
            #pragma unroll 8
            for (int c = 0; c < 64; c++) a += s_pool[j][c] * k1w[tid * 64 + c];
            s_h1[tid] = fmaxf(a, 0.f); }
        __syncthreads();
        if (tid < 128) {
            float a = k2b[tid];
            #pragma unroll 8
            for (int c = 0; c < 256; c++) a += s_h1[c] * k2w[tid * 256 + c];
            s_h2[tid] = fmaxf(a, 0.f);
        }
        __syncthreads();
        {   float a = k3b[tid];
            #pragma unroll 8
            for (int c = 0; c < 128; c++) a += s_h2[c] * k3w[tid * 128 + c];
            s_key[j][tid] = a; }
        __syncthreads();
    }

    // query from first image of this batch
    {   float a = q1b[tid];
        #pragma unroll 8
        for (int c = 0; c < 64; c++) a += s_pool[0][c] * q1w[tid * 64 + c];
        s_h1[tid] = fmaxf(a, 0.f); }
    __syncthreads();
    if (tid < 128) {
        float a = q2b[tid];
        #pragma unroll 8
        for (int c = 0; c < 256; c++) a += s_h1[c] * q2w[tid * 256 + c];
        s_h2[tid] = fmaxf(a, 0.f);
    }
    __syncthreads();
    if (tid < 32) {
        float a = q3b[tid];
        #pragma unroll 8
        for (int c = 0; c < 128; c++) a += s_h2[c] * q3w[tid * 128 + c];
        s_qry[tid] = a;
    }
    __syncthreads();
    {   float a = ab[tid];
        #pragma unroll
        for (int m = 0; m < 32; m++) a += s_qry[m] * aw[tid * 32 + m];
        s_q[tid] = a; }
    __syncthreads();

    // logits + softmax over 5
    if (warp < 5) {
        float s = 0.f;
        for (int k = lane; k < 256; k += 32) s += s_key[warp][k] * s_q[k];
        #pragma unroll
        for (int o = 16; o; o >>= 1) s += __shfl_xor_sync(0xFFFFFFFFu, s, o);
        if (lane == 0) s_log[warp] = s;
    }
    __syncthreads();
    if (tid == 0) {
        float mx = s_log[0];
        #pragma unroll
        for (int j = 1; j < 5; j++) mx = fmaxf(mx, s_log[j]);
        float e[5], sum = 0.f;
        #pragma unroll
        for (int j = 0; j < 5; j++) { e[j] = __expf(s_log[j] - mx); sum += e[j]; }
        float inv = 1.0f / sum;
        #pragma unroll
        for (int j = 0; j < 5; j++) g_attn[b * 5 + j] = e[j] * inv;
    }
}

// ---------------- K6: attention-weighted fusion ----------------
__global__ void k_fuse(float* __restrict__ out) {
    size_t idx = (size_t)blockIdx.x * 256 + threadIdx.x;   // over float4s
    const size_t per_b = (size_t)CIN * HH * WW / 4;        // 524288
    int b = (int)(idx / per_b);
    size_t r = idx - (size_t)b * per_b;
    float a0 = __ldg(&g_attn[b * 5 + 0]);
    float a1 = __ldg(&g_attn[b * 5 + 1]);
    float a2 = __ldg(&g_attn[b * 5 + 2]);
    float a3 = __ldg(&g_attn[b * 5 + 3]);
    float a4 = __ldg(&g_attn[b * 5 + 4]);
    const float4* base = (const float4*)g_neigh + (size_t)b * 5 * per_b + r;
    float4 v0 = base[0 * per_b], v1 = base[1 * per_b], v2 = base[2 * per_b];
    float4 v3 = base[3 * per_b], v4 = base[4 * per_b];
    float4 o;
    o.x = a0 * v0.x + a1 * v1.x + a2 * v2.x + a3 * v3.x + a4 * v4.x;
    o.y = a0 * v0.y + a1 * v1.y + a2 * v2.y + a3 * v3.y + a4 * v4.y;
    o.z = a0 * v0.z + a1 * v1.z + a2 * v2.z + a3 * v3.z + a4 * v4.z;
    o.w = a0 * v0.w + a1 * v1.w + a2 * v2.w + a3 * v3.w + a4 * v4.w;
    ((float4*)out)[idx] = o;
}

// ---------------- launch ----------------
extern "C" void kernel_launch(void* const* d_in, const int* in_sizes, int n_in,
                              void* d_out, int out_size) {
    const float* x    = (const float*)d_in[0];
    // d_in[1] = record_len (int32) — unused (reference ignores it, all = L)
    const float* nam  = (const float*)d_in[2];
    const float* c1w  = (const float*)d_in[3];
    const float* c1b  = (const float*)d_in[4];
    const float* c2w  = (const float*)d_in[5];
    const float* c2b  = (const float*)d_in[6];
    const float* c3w  = (const float*)d_in[7];
    const float* c3b  = (const float*)d_in[8];
    const float* k1w  = (const float*)d_in[9];
    const float* k1b  = (const float*)d_in[10];
    const float* k2w  = (const float*)d_in[11];
    const float* k2b  = (const float*)d_in[12];
    const float* k3w  = (const float*)d_in[13];
    const float* k3b  = (const float*)d_in[14];
    const float* q1w  = (const float*)d_in[15];
    const float* q1b  = (const float*)d_in[16];
    const float* q2w  = (const float*)d_in[17];
    const float* q2b  = (const float*)d_in[18];
    const float* q3w  = (const float*)d_in[19];
    const float* q3b  = (const float*)d_in[20];
    const float* aw   = (const float*)d_in[21];
    const float* abv  = (const float*)d_in[22];
    float* out = (float*)d_out;

    k_gridsample<<<dim3(HH, NN), WW>>>(x, nam);
    k_conv1<<<dim3(128, NN), 64>>>(c1w, c1b);
    k_conv2<<<dim3(32, NN), 64>>>(c2w, c2b);
    k_conv3<<<dim3(8, NN), 128>>>(c3w, c3b);
    k_attn<<<BB, 256>>>(k1w, k1b, k2w, k2b, k3w, k3b,
                        q1w, q1b, q2w, q2b, q3w, q3b, aw, abv);
    k_fuse<<<(int)((size_t)BB * CIN * HH * WW / 4 / 256), 256>>>(out);
}

// round 6
// speedup vs baseline: 1.9787x; 1.9787x over previous
#include <cuda_runtime.h>
#include <cuda_bf16.h>
#include <math.h>
#include <stdint.h>

#define BB 4
#define LL 5
#define NN 20      // B*L
#define CIN 64
#define HH 256
#define WW 128

// ---------------- scratch (device globals; no allocation) ----------------
__device__ __nv_bfloat16 g_nb[NN * CIN * HH * WW];   // bf16 sampled neigh (~84MB)
__device__ __nv_bfloat16 g_m1[NN * 32 * 128 * 64];   // conv1 out (bf16)
__device__ __nv_bfloat16 g_m2[NN * 64 * 64 * 32];    // conv2 out (bf16)
__device__ float         g_m3[NN * 64 * 32 * 16];    // conv3 out (f32, for pooling)
__device__ float         g_attn[NN];                 // softmax weights
// packed B fragments: [ic][ocg][lane][2] uint32
__device__ uint32_t g_wp1[64 * 4 * 32 * 2];
__device__ uint32_t g_wp2[32 * 8 * 32 * 2];
__device__ uint32_t g_wp3[64 * 8 * 32 * 2];

// ---------------- K0: pack conv weights into mma B-fragment layout ----------------
// B fragment (m16n8k16, col): reg0 = (k=2t, n=g),(k=2t+1, n=g); reg1 = k+8.
// k ordering: c = ky*4+kx (matches A im2col ordering). oc = ocg*8 + g.
__device__ __forceinline__ void pack_one(const float* w, uint32_t* dst,
                                         int IC, int OCG, int e) {
    int lane = e & 31;
    int ocg  = (e >> 5) % OCG;
    int ic   = (e >> 5) / OCG;
    int g = lane >> 2, t = lane & 3;
    int oc = ocg * 8 + g;
    const float* wb = w + ((size_t)oc * IC + ic) * 16;
    uint32_t l0 = __bfloat16_as_ushort(__float2bfloat16(wb[2 * t]));
    uint32_t h0 = __bfloat16_as_ushort(__float2bfloat16(wb[2 * t + 1]));
    uint32_t l1 = __bfloat16_as_ushort(__float2bfloat16(wb[2 * t + 8]));
    uint32_t h1 = __bfloat16_as_ushort(__float2bfloat16(wb[2 * t + 9]));
    int o = ((ic * OCG + ocg) * 32 + lane) * 2;
    dst[o]     = l0 | (h0 << 16);
    dst[o + 1] = l1 | (h1 << 16);
}

__global__ void k_pack(const float* __restrict__ w1, const float* __restrict__ w2,
                       const float* __restrict__ w3) {
    int idx = blockIdx.x * 256 + threadIdx.x;   // 32768 entries total
    if (idx < 8192)            pack_one(w1, g_wp1, 64, 4, idx);
    else if (idx < 16384)      pack_one(w2, g_wp2, 32, 8, idx - 8192);
    else if (idx < 32768)      pack_one(w3, g_wp3, 64, 8, idx - 16384);
}

// ---------------- K1: affine grid sample -> bf16 ----------------
__global__ void k_gridsample(const float* __restrict__ x, const float* __restrict__ nam) {
    int n  = blockIdx.y;       // 0..19
    int yy = blockIdx.x;       // 0..255
    int xx = threadIdx.x;      // 0..127
    int b = n / LL, nl = n % LL;
    const float* t = nam + ((size_t)(b * LL * LL) + nl) * 6;   // nam[b][0][nl]
    float t00 = t[0], t01 = t[1], t02 = t[2];
    float t10 = t[3], t11 = t[4], t12 = t[5];

    float gx = (xx + 0.5f) * (2.0f / WW) - 1.0f;
    float gy = (yy + 0.5f) * (2.0f / HH) - 1.0f;
    float sx = (((t00 * gx + t01 * gy + t02) + 1.0f) * WW - 1.0f) * 0.5f;
    float sy = (((t10 * gx + t11 * gy + t12) + 1.0f) * HH - 1.0f) * 0.5f;
    float x0f = floorf(sx), y0f = floorf(sy);
    int ix0 = (int)x0f, iy0 = (int)y0f;
    int ix1 = ix0 + 1, iy1 = iy0 + 1;
    float wx1 = sx - x0f, wx0 = 1.0f - wx1;
    float wy1 = sy - y0f, wy0 = 1.0f - wy1;
    bool vx0 = (ix0 >= 0) && (ix0 < WW), vx1 = (ix1 >= 0) && (ix1 < WW);
    bool vy0 = (iy0 >= 0) && (iy0 < HH), vy1 = (iy1 >= 0) && (iy1 < HH);
    float w00 = wx0 * wy0 * ((vx0 && vy0) ? 1.f : 0.f);
    float w10 = wx1 * wy0 * ((vx1 && vy0) ? 1.f : 0.f);
    float w01 = wx0 * wy1 * ((vx0 && vy1) ? 1.f : 0.f);
    float w11 = wx1 * wy1 * ((vx1 && vy1) ? 1.f : 0.f);
    int cx0 = min(max(ix0, 0), WW - 1), cx1 = min(max(ix1, 0), WW - 1);
    int cy0 = min(max(iy0, 0), HH - 1), cy1 = min(max(iy1, 0), HH - 1);

    size_t base = (size_t)n * CIN * HH * WW;
    int o00 = cy0 * WW + cx0, o10 = cy0 * WW + cx1;
    int o01 = cy1 * WW + cx0, o11 = cy1 * WW + cx1;
    size_t ob = base + (size_t)yy * WW + xx;
    #pragma unroll 4
    for (int c = 0; c < CIN; c++) {
        const float* p = x + base + (size_t)c * (HH * WW);
        float v = w00 * p[o00] + w10 * p[o10] + w01 * p[o01] + w11 * p[o11];
        g_nb[ob + (size_t)c * (HH * WW)] = __float2bfloat16(v);
    }
}

// ---------------- conv: implicit GEMM with mma.sync m16n8k16 bf16 ----------------
// 4x4 conv, stride 2, pad 1.  Block = 256 threads = 8 warps; block covers
// ROWS output rows x OW cols = 128 px, all OC channels. K = IC*16 (c = ky*4+kx),
// chunked CH=8 ics per smem stage.  Input staged as shifted b32 words so that
// word q = (elem 2q-1, elem 2q) -> A-fragment pairs are aligned LDS.32.
template<int IC, int OC, int IH, int IW, int ROWS, int LAYER>
__global__ void __launch_bounds__(256, 1) k_conv(const float* __restrict__ bias) {
    constexpr int OH  = IH / 2, OW = IW / 2;
    constexpr int OCG = OC / 8;
    constexpr int CH  = 8;
    constexpr int R_IN = 2 * ROWS + 2;
    constexpr int WA  = IW / 2;       // aligned words per row
    constexpr int WQ  = WA + 1;       // shifted words per row
    constexpr int WPS = WQ + 1;       // padded stride
    __shared__ uint32_t s_align[CH * R_IN * WA];
    __shared__ uint32_t s_raw[CH * R_IN * WPS];
    __shared__ uint32_t s_B[CH * OCG * 64];

    const __nv_bfloat16* in = (LAYER == 1) ? g_nb : (LAYER == 2) ? g_m1 : g_m2;
    const uint32_t* wpack   = (LAYER == 1) ? g_wp1 : (LAYER == 2) ? g_wp2 : g_wp3;

    int n   = blockIdx.y;
    int oy0 = blockIdx.x * ROWS;
    int tid = threadIdx.x;
    int wid = tid >> 5, lane = tid & 31;
    int g = lane >> 2, t = lane & 3;
    int ky0 = t >> 1, kxp = t & 1;
    int ry  = (wid * 16) / OW;
    int wox = (wid * 16) % OW;
    int ox  = wox + g;
    int oy  = oy0 + ry;
    int iy0 = 2 * oy0 - 1;

    float4 acc[OCG];
    #pragma unroll
    for (int i = 0; i < OCG; i++) acc[i] = make_float4(0.f, 0.f, 0.f, 0.f);

    const uint32_t* in32 = reinterpret_cast<const uint32_t*>(in) + (size_t)n * IC * IH * WA;
    int p0 = (2 * ry + ky0) * WPS + ox + kxp;

    for (int cc = 0; cc < IC / CH; cc++) {
        int ic0 = cc * CH;
        __syncthreads();
        // stage aligned input words (coalesced b32 LDG)
        for (int i = tid; i < CH * R_IN * WA; i += 256) {
            int icl = i / (R_IN * WA); int rem = i % (R_IN * WA);
            int r = rem / WA; int wq = rem % WA;
            int iy = iy0 + r;
            uint32_t v = 0;
            if (iy >= 0 && iy < IH) v = in32[((size_t)(ic0 + icl) * IH + iy) * WA + wq];
            s_align[(icl * R_IN + r) * WA + wq] = v;
        }
        // stage packed B fragments
        {
            const uint32_t* src = wpack + (size_t)ic0 * OCG * 64;
            for (int i = tid; i < CH * OCG * 64; i += 256) s_B[i] = src[i];
        }
        __syncthreads();
        // build shifted words: word q = (elem 2q-1, elem 2q), zero-padded borders
        for (int i = tid; i < CH * R_IN * WQ; i += 256) {
            int icl = i / (R_IN * WQ); int rem = i % (R_IN * WQ);
            int r = rem / WQ; int q = rem % WQ;
            const unsigned short* ah =
                reinterpret_cast<const unsigned short*>(&s_align[(icl * R_IN + r) * WA]);
            uint32_t lo = (q == 0)  ? 0u : (uint32_t)ah[2 * q - 1];
            uint32_t hi = (q == WA) ? 0u : (uint32_t)ah[2 * q];
            s_raw[(icl * R_IN + r) * WPS + q] = lo | (hi << 16);
        }
        __syncthreads();
        // consume: per ic one K16 step; A frag = 4 aligned LDS.32, B from s_B
        #pragma unroll
        for (int icl = 0; icl < CH; icl++) {
            const uint32_t* rb = s_raw + icl * R_IN * WPS;
            uint32_t a0 = rb[p0];
            uint32_t a1 = rb[p0 + 8];
            uint32_t a2 = rb[p0 + 2 * WPS];
            uint32_t a3 = rb[p0 + 2 * WPS + 8];
            const uint32_t* bb = s_B + icl * OCG * 64 + lane * 2;
            #pragma unroll
            for (int ocg = 0; ocg < OCG; ocg++) {
                uint32_t b0 = bb[ocg * 64], b1 = bb[ocg * 64 + 1];
                asm volatile(
                    "mma.sync.aligned.m16n8k16.row.col.f32.bf16.bf16.f32 "
                    "{%0,%1,%2,%3}, {%4,%5,%6,%7}, {%8,%9}, {%0,%1,%2,%3};\n"
                    : "+f"(acc[ocg].x), "+f"(acc[ocg].y),
                      "+f"(acc[ocg].z), "+f"(acc[ocg].w)
                    : "r"(a0), "r"(a1), "r"(a2), "r"(a3), "r"(b0), "r"(b1));
            }
        }
    }
    // epilogue: C frag: (row g, oc0), (row g, oc0+1), (row g+8, oc0), (row g+8, oc0+1)
    const size_t plane = (size_t)OH * OW;
    #pragma unroll
    for (int ocg = 0; ocg < OCG; ocg++) {
        int oc0 = ocg * 8 + 2 * t;
        float bv0 = bias[oc0], bv1 = bias[oc0 + 1];
        size_t base0 = ((size_t)n * OC + oc0) * plane + (size_t)oy * OW;
        float v00 = fmaxf(acc[ocg].x + bv0, 0.f);
        float v01 = fmaxf(acc[ocg].y + bv1, 0.f);
        float v10 = fmaxf(acc[ocg].z + bv0, 0.f);
        float v11 = fmaxf(acc[ocg].w + bv1, 0.f);
        if (LAYER == 3) {
            g_m3[base0 + ox]             = v00;
            g_m3[base0 + plane + ox]     = v01;
            g_m3[base0 + ox + 8]         = v10;
            g_m3[base0 + plane + ox + 8] = v11;
        } else if (LAYER == 2) {
            g_m2[base0 + ox]             = __float2bfloat16(v00);
            g_m2[base0 + plane + ox]     = __float2bfloat16(v01);
            g_m2[base0 + ox + 8]         = __float2bfloat16(v10);
            g_m2[base0 + plane + ox + 8] = __float2bfloat16(v11);
        } else {
            g_m1[base0 + ox]             = __float2bfloat16(v00);
            g_m1[base0 + plane + ox]     = __float2bfloat16(v01);
            g_m1[base0 + ox + 8]         = __float2bfloat16(v10);
            g_m1[base0 + plane + ox + 8] = __float2bfloat16(v11);
        }
    }
}

// ---------------- K5: pool + key/qry MLPs + attention softmax ----------------
__global__ void k_attn(const float* __restrict__ k1w, const float* __restrict__ k1b,
                       const float* __restrict__ k2w, const float* __restrict__ k2b,
                       const float* __restrict__ k3w, const float* __restrict__ k3b,
                       const float* __restrict__ q1w, const float* __restrict__ q1b,
                       const float* __restrict__ q2w, const float* __restrict__ q2b,
                       const float* __restrict__ q3w, const float* __restrict__ q3b,
                       const float* __restrict__ aw,  const float* __restrict__ ab) {
    int b = blockIdx.x;
    int tid = threadIdx.x;
    int warp = tid >> 5, lane = tid & 31;
    __shared__ float s_pool[5][64];
    __shared__ float s_key[5][256];
    __shared__ float s_h1[256];
    __shared__ float s_h2[128];
    __shared__ float s_qry[32];
    __shared__ float s_q[256];
    __shared__ float s_log[5];

    for (int tk = warp; tk < 5 * 64; tk += 8) {
        int j = tk >> 6, c = tk & 63;
        const float* p = g_m3 + ((size_t)((b * 5 + j) * 64 + c)) * 512;
        float s = 0.f;
        for (int k = lane; k < 512; k += 32) s += p[k];
        #pragma unroll
        for (int o = 16; o; o >>= 1) s += __shfl_xor_sync(0xFFFFFFFFu, s, o);
        if (lane == 0) s_pool[j][c] = s * (1.0f / 512.0f);
    }
    __syncthreads();

    for (int j = 0; j < 5; j++) {
        {   float a = k1b[tid];
            #pragma unroll 8
            for (int c = 0; c < 64; c++) a += s_pool[j][c] * k1w[tid * 64 + c];
            s_h1[tid] = fmaxf(a, 0.f); }
        __syncthreads();
        if (tid < 128) {
            float a = k2b[tid];
            #pragma unroll 8
            for (int c = 0; c < 256; c++) a += s_h1[c] * k2w[tid * 256 + c];
            s_h2[tid] = fmaxf(a, 0.f);
        }
        __syncthreads();
        {   float a = k3b[tid];
            #pragma unroll 8
            for (int c = 0; c < 128; c++) a += s_h2[c] * k3w[tid * 128 + c];
            s_key[j][tid] = a; }
        __syncthreads();
    }

    {   float a = q1b[tid];
        #pragma unroll 8
        for (int c = 0; c < 64; c++) a += s_pool[0][c] * q1w[tid * 64 + c];
        s_h1[tid] = fmaxf(a, 0.f); }
    __syncthreads();
    if (tid < 128) {
        float a = q2b[tid];
        #pragma unroll 8
        for (int c = 0; c < 256; c++) a += s_h1[c] * q2w[tid * 256 + c];
        s_h2[tid] = fmaxf(a, 0.f);
    }
    __syncthreads();
    if (tid < 32) {
        float a = q3b[tid];
        #pragma unroll 8
        for (int c = 0; c < 128; c++) a += s_h2[c] * q3w[tid * 128 + c];
        s_qry[tid] = a;
    }
    __syncthreads();
    {   float a = ab[tid];
        #pragma unroll
        for (int m = 0; m < 32; m++) a += s_qry[m] * aw[tid * 32 + m];
        s_q[tid] = a; }
    __syncthreads();

    if (warp < 5) {
        float s = 0.f;
        for (int k = lane; k < 256; k += 32) s += s_key[warp][k] * s_q[k];
        #pragma unroll
        for (int o = 16; o; o >>= 1) s += __shfl_xor_sync(0xFFFFFFFFu, s, o);
        if (lane == 0) s_log[warp] = s;
    }
    __syncthreads();
    if (tid == 0) {
        float mx = s_log[0];
        #pragma unroll
        for (int j = 1; j < 5; j++) mx = fmaxf(mx, s_log[j]);
        float e[5], sum = 0.f;
        #pragma unroll
        for (int j = 0; j < 5; j++) { e[j] = __expf(s_log[j] - mx); sum += e[j]; }
        float inv = 1.0f / sum;
        #pragma unroll
        for (int j = 0; j < 5; j++) g_attn[b * 5 + j] = e[j] * inv;
    }
}

// ---------------- K6: fused bilinear-resample + attention-weighted sum (exact f32) ----
__global__ void k_fuse(const float* __restrict__ x, const float* __restrict__ nam,
                       float* __restrict__ out) {
    int b  = blockIdx.y;
    int yy = blockIdx.x;
    int xx = threadIdx.x;

    float W00[5], W10[5], W01[5], W11[5];
    int   O00[5], O10[5], O01[5], O11[5];
    float gx = (xx + 0.5f) * (2.0f / WW) - 1.0f;
    float gy = (yy + 0.5f) * (2.0f / HH) - 1.0f;
    #pragma unroll
    for (int j = 0; j < 5; j++) {
        float a = g_attn[b * 5 + j];
        const float* t = nam + ((size_t)(b * LL * LL) + j) * 6;
        float sx = (((t[0] * gx + t[1] * gy + t[2]) + 1.0f) * WW - 1.0f) * 0.5f;
        float sy = (((t[3] * gx + t[4] * gy + t[5]) + 1.0f) * HH - 1.0f) * 0.5f;
        float x0f = floorf(sx), y0f = floorf(sy);
        int ix0 = (int)x0f, iy0 = (int)y0f;
        int ix1 = ix0 + 1, iy1 = iy0 + 1;
        float wx1 = sx - x0f, wx0 = 1.0f - wx1;
        float wy1 = sy - y0f, wy0 = 1.0f - wy1;
        bool vx0 = (ix0 >= 0) && (ix0 < WW), vx1 = (ix1 >= 0) && (ix1 < WW);
        bool vy0 = (iy0 >= 0) && (iy0 < HH), vy1 = (iy1 >= 0) && (iy1 < HH);
        W00[j] = a * wx0 * wy0 * ((vx0 && vy0) ? 1.f : 0.f);
        W10[j] = a * wx1 * wy0 * ((vx1 && vy0) ? 1.f : 0.f);
        W01[j] = a * wx0 * wy1 * ((vx0 && vy1) ? 1.f : 0.f);
        W11[j] = a * wx1 * wy1 * ((vx1 && vy1) ? 1.f : 0.f);
        int cx0 = min(max(ix0, 0), WW - 1), cx1 = min(max(ix1, 0), WW - 1);
        int cy0 = min(max(iy0, 0), HH - 1), cy1 = min(max(iy1, 0), HH - 1);
        O00[j] = cy0 * WW + cx0; O10[j] = cy0 * WW + cx1;
        O01[j] = cy1 * WW + cx0; O11[j] = cy1 * WW + cx1;
    }

    for (int c = 0; c < CIN; c++) {
        float acc = 0.f;
        #pragma unroll
        for (int j = 0; j < 5; j++) {
            const float* p = x + ((size_t)((b * 5 + j) * CIN) + c) * (HH * WW);
            acc += W00[j] * p[O00[j]] + W10[j] * p[O10[j]]
                 + W01[j] * p[O01[j]] + W11[j] * p[O11[j]];
        }
        out[((size_t)(b * CIN + c) * HH + yy) * WW + xx] = acc;
    }
}

// ---------------- launch ----------------
extern "C" void kernel_launch(void* const* d_in, const int* in_sizes, int n_in,
                              void* d_out, int out_size) {
    const float* x    = (const float*)d_in[0];
    // d_in[1] = record_len (int32) — unused (reference ignores it, all = L)
    const float* nam  = (const float*)d_in[2];
    const float* c1w  = (const float*)d_in[3];
    const float* c1b  = (const float*)d_in[4];
    const float* c2w  = (const float*)d_in[5];
    const float* c2b  = (const float*)d_in[6];
    const float* c3w  = (const float*)d_in[7];
    const float* c3b  = (const float*)d_in[8];
    const float* k1w  = (const float*)d_in[9];
    const float* k1b  = (const float*)d_in[10];
    const float* k2w  = (const float*)d_in[11];
    const float* k2b  = (const float*)d_in[12];
    const float* k3w  = (const float*)d_in[13];
    const float* k3b  = (const float*)d_in[14];
    const float* q1w  = (const float*)d_in[15];
    const float* q1b  = (const float*)d_in[16];
    const float* q2w  = (const float*)d_in[17];
    const float* q2b  = (const float*)d_in[18];
    const float* q3w  = (const float*)d_in[19];
    const float* q3b  = (const float*)d_in[20];
    const float* aw   = (const float*)d_in[21];
    const float* abv  = (const float*)d_in[22];
    float* out = (float*)d_out;

    k_pack<<<128, 256>>>(c1w, c2w, c3w);
    k_gridsample<<<dim3(HH, NN), WW>>>(x, nam);
    k_conv<64, 32, 256, 128, 2, 1><<<dim3(64, NN), 256>>>(c1b);
    k_conv<32, 64, 128,  64, 4, 2><<<dim3(16, NN), 256>>>(c2b);
    k_conv<64, 64,  64,  32, 8, 3><<<dim3(4,  NN), 256>>>(c3b);
    k_attn<<<BB, 256>>>(k1w, k1b, k2w, k2b, k3w, k3b,
                        q1w, q1b, q2w, q2b, q3w, q3b, aw, abv);
    k_fuse<<<dim3(HH, BB), WW>>>(x, nam, out);
}